// round 1
// baseline (speedup 1.0000x reference)
#include <cuda_runtime.h>
#include <cuda_bf16.h>
#include <math.h>

// Problem dims (fixed by reference)
#define B_   16
#define C_   256
#define N_   1024          // 32*32 tokens
#define BN_  (B_*N_)       // 16384
#define INNER 128          // HEADS*DIM_HEAD
#define HEADS 4
#define DHEAD 32

// ---------------- scratch (device globals; no allocation allowed) ----------
__device__ __align__(16) float g_tok[BN_ * C_];     // residual stream [B,N,C]
__device__ __align__(16) float g_ln [BN_ * C_];     // layernorm output
__device__ __align__(16) float g_qkv[BN_ * 384];    // qkv projection
__device__ __align__(16) float g_att[BN_ * INNER];  // attention output
__device__ __align__(16) float g_hdn[BN_ * INNER];  // ff hidden

// ---------------- kernel 1: x[b,c,n] -> tok[b,n,c] (+pos) ------------------
__global__ void transpose_in_kernel(const float* __restrict__ x,
                                    const float* __restrict__ pos) {
    __shared__ float tile[32][33];
    int b  = blockIdx.z;
    int n0 = blockIdx.x * 32;
    int c0 = blockIdx.y * 32;
    int tx = threadIdx.x, ty = threadIdx.y;
    const float* xb = x + (size_t)b * C_ * N_;
    #pragma unroll
    for (int i = 0; i < 4; ++i) {
        int c = c0 + ty + i * 8;
        tile[ty + i * 8][tx] = xb[(size_t)c * N_ + n0 + tx];
    }
    __syncthreads();
    float* tb = g_tok + (size_t)b * N_ * C_;
    #pragma unroll
    for (int i = 0; i < 4; ++i) {
        int n = n0 + ty + i * 8;
        int c = c0 + tx;
        tb[(size_t)n * C_ + c] = tile[tx][ty + i * 8] + pos[(size_t)n * C_ + c];
    }
}

// ---------------- kernel: layernorm per token (C=256) ----------------------
__global__ void ln_kernel(const float* __restrict__ in,
                          const float* __restrict__ g,
                          const float* __restrict__ beta,
                          float* __restrict__ out) {
    int t = blockIdx.x;
    int c = threadIdx.x;
    const float* row = in + (size_t)t * C_;
    float v = row[c];
    float s = v, s2 = v * v;
    #pragma unroll
    for (int off = 16; off; off >>= 1) {
        s  += __shfl_xor_sync(0xffffffffu, s,  off);
        s2 += __shfl_xor_sync(0xffffffffu, s2, off);
    }
    __shared__ float ws[8], ws2[8];
    int w = c >> 5, lane = c & 31;
    if (lane == 0) { ws[w] = s; ws2[w] = s2; }
    __syncthreads();
    if (w == 0) {
        s  = (lane < 8) ? ws[lane]  : 0.f;
        s2 = (lane < 8) ? ws2[lane] : 0.f;
        #pragma unroll
        for (int off = 4; off; off >>= 1) {
            s  += __shfl_xor_sync(0xffffffffu, s,  off);
            s2 += __shfl_xor_sync(0xffffffffu, s2, off);
        }
        if (lane == 0) {
            float mu  = s * (1.f / C_);
            float var = s2 * (1.f / C_) - mu * mu;
            ws[0]  = mu;
            ws2[0] = rsqrtf(var + 1e-5f);
        }
    }
    __syncthreads();
    float mu = ws[0], r = ws2[0];
    out[(size_t)t * C_ + c] = (v - mu) * r * g[c] + beta[c];
}

// ---------------- generic register-tiled SGEMM -----------------------------
// C[M,Nc] = A[M,K] @ W[K,Nc]   (+ epilogue)
// EPI: 0 plain, 1 +bias+resid, 2 gelu(.+bias)
#define BM 64
#define BN 64
#define BKT 16
template <int EPI>
__global__ __launch_bounds__(256) void sgemm_kernel(
        const float* __restrict__ A, const float* __restrict__ W,
        const float* __restrict__ bias, const float* __restrict__ resid,
        float* __restrict__ C, int M, int K, int Nc) {
    __shared__ float As[BKT][BM];
    __shared__ float Bs[BKT][BN];
    int tid = threadIdx.x;
    int tx = tid & 15, ty = tid >> 4;
    int m0 = blockIdx.y * BM, n0 = blockIdx.x * BN;
    int arow = tid >> 2;              // 0..63
    int acol = (tid & 3) * 4;         // 0..12
    int brow = tid >> 4;              // 0..15
    int bcol = (tid & 15) * 4;        // 0..60
    float acc[4][4] = {};
    const float* Aptr = A + (size_t)(m0 + arow) * K + acol;
    const float* Bptr = W + (size_t)brow * Nc + n0 + bcol;
    for (int k0 = 0; k0 < K; k0 += BKT) {
        float4 av = *(const float4*)(Aptr + k0);
        float4 bv = *(const float4*)(Bptr + (size_t)k0 * Nc);
        As[acol + 0][arow] = av.x;
        As[acol + 1][arow] = av.y;
        As[acol + 2][arow] = av.z;
        As[acol + 3][arow] = av.w;
        *(float4*)&Bs[brow][bcol] = bv;
        __syncthreads();
        #pragma unroll
        for (int k = 0; k < BKT; ++k) {
            float4 a = *(const float4*)&As[k][ty * 4];
            float4 b = *(const float4*)&Bs[k][tx * 4];
            float ar[4] = {a.x, a.y, a.z, a.w};
            float br[4] = {b.x, b.y, b.z, b.w};
            #pragma unroll
            for (int i = 0; i < 4; ++i)
                #pragma unroll
                for (int j = 0; j < 4; ++j)
                    acc[i][j] += ar[i] * br[j];
        }
        __syncthreads();
    }
    #pragma unroll
    for (int i = 0; i < 4; ++i) {
        int row = m0 + ty * 4 + i;
        #pragma unroll
        for (int j = 0; j < 4; ++j) {
            int col = n0 + tx * 4 + j;
            size_t idx = (size_t)row * Nc + col;
            float v = acc[i][j];
            if (EPI == 1) v += bias[col] + resid[idx];
            else if (EPI == 2) {
                v += bias[col];
                v = 0.5f * v * (1.f + erff(v * 0.7071067811865475f));
            }
            C[idx] = v;
        }
    }
}

// ---------------- fused flash attention ------------------------------------
// grid (N/256, HEADS, B), 256 threads; 1 query per thread; K/V tiles of 128.
__global__ __launch_bounds__(256) void attn_kernel(const float* __restrict__ qkv,
                                                   float* __restrict__ out) {
    int b = blockIdx.z, h = blockIdx.y;
    int t = threadIdx.x;
    int qi = blockIdx.x * 256 + t;
    const float SCALE = 0.17677669529663687f;  // 1/sqrt(32)
    __shared__ float Ks[128][32];
    __shared__ float Vs[128][32];
    float q[32], o[32];
    {
        const float4* qrow = (const float4*)(qkv + (size_t)(b * N_ + qi) * 384 + h * DHEAD);
        #pragma unroll
        for (int i = 0; i < 8; ++i) {
            float4 v = qrow[i];
            q[4 * i + 0] = v.x * SCALE;
            q[4 * i + 1] = v.y * SCALE;
            q[4 * i + 2] = v.z * SCALE;
            q[4 * i + 3] = v.w * SCALE;
        }
    }
    #pragma unroll
    for (int d = 0; d < 32; ++d) o[d] = 0.f;
    float m = -1e30f, l = 0.f;
    int r  = t >> 1;
    int cb = (t & 1) * 4;  // float4 index offset (covers 16 floats)
    for (int k0 = 0; k0 < N_; k0 += 128) {
        __syncthreads();
        const float4* krow = (const float4*)(qkv + (size_t)(b * N_ + k0 + r) * 384 + 128 + h * DHEAD);
        const float4* vrow = (const float4*)(qkv + (size_t)(b * N_ + k0 + r) * 384 + 256 + h * DHEAD);
        float4* kd = (float4*)&Ks[r][cb * 4];
        float4* vd = (float4*)&Vs[r][cb * 4];
        #pragma unroll
        for (int i = 0; i < 4; ++i) {
            kd[i] = krow[cb + i];
            vd[i] = vrow[cb + i];
        }
        __syncthreads();
        for (int j = 0; j < 128; ++j) {
            const float4* kj = (const float4*)Ks[j];
            float s0 = 0, s1 = 0, s2 = 0, s3 = 0;
            #pragma unroll
            for (int i = 0; i < 8; ++i) {
                float4 kv = kj[i];
                s0 += q[4 * i + 0] * kv.x;
                s1 += q[4 * i + 1] * kv.y;
                s2 += q[4 * i + 2] * kv.z;
                s3 += q[4 * i + 3] * kv.w;
            }
            float s = (s0 + s1) + (s2 + s3);
            if (s > m) {
                float corr = __expf(m - s);
                m = s;
                l *= corr;
                #pragma unroll
                for (int d = 0; d < 32; ++d) o[d] *= corr;
            }
            float e = __expf(s - m);
            l += e;
            const float4* vj = (const float4*)Vs[j];
            #pragma unroll
            for (int i = 0; i < 8; ++i) {
                float4 vv = vj[i];
                o[4 * i + 0] += e * vv.x;
                o[4 * i + 1] += e * vv.y;
                o[4 * i + 2] += e * vv.z;
                o[4 * i + 3] += e * vv.w;
            }
        }
    }
    float inv = 1.f / l;
    float4* orow = (float4*)(out + (size_t)(b * N_ + qi) * INNER + h * DHEAD);
    #pragma unroll
    for (int i = 0; i < 8; ++i) {
        float4 v;
        v.x = o[4 * i + 0] * inv;
        v.y = o[4 * i + 1] * inv;
        v.z = o[4 * i + 2] * inv;
        v.w = o[4 * i + 3] * inv;
        orow[i] = v;
    }
}

// ---------------- final: tok[b,n,c] -> out[b,c,n] ---------------------------
__global__ void transpose_out_kernel(float* __restrict__ out) {
    __shared__ float tile[32][33];
    int b  = blockIdx.z;
    int n0 = blockIdx.x * 32;
    int c0 = blockIdx.y * 32;
    int tx = threadIdx.x, ty = threadIdx.y;
    const float* tb = g_tok + (size_t)b * N_ * C_;
    #pragma unroll
    for (int i = 0; i < 4; ++i) {
        int n = n0 + ty + i * 8;
        tile[ty + i * 8][tx] = tb[(size_t)n * C_ + c0 + tx];
    }
    __syncthreads();
    float* ob = out + (size_t)b * C_ * N_;
    #pragma unroll
    for (int i = 0; i < 4; ++i) {
        int c = c0 + ty + i * 8;
        ob[(size_t)c * N_ + n0 + tx] = tile[tx][ty + i * 8];
    }
}

// ---------------------------------------------------------------------------
extern "C" void kernel_launch(void* const* d_in, const int* in_sizes, int n_in,
                              void* d_out, int out_size) {
    const float* x     = (const float*)d_in[0];
    const float* pos   = (const float*)d_in[1];
    const float* w_qkv = (const float*)d_in[2];
    const float* w_out = (const float*)d_in[3];
    const float* b_out = (const float*)d_in[4];
    const float* w_ff1 = (const float*)d_in[5];
    const float* b_ff1 = (const float*)d_in[6];
    const float* w_ff2 = (const float*)d_in[7];
    const float* b_ff2 = (const float*)d_in[8];
    const float* g1    = (const float*)d_in[9];
    const float* beta1 = (const float*)d_in[10];
    const float* g2    = (const float*)d_in[11];
    const float* beta2 = (const float*)d_in[12];
    float* out = (float*)d_out;

    float *tok, *ln, *qkv, *att, *hdn;
    cudaGetSymbolAddress((void**)&tok, g_tok);
    cudaGetSymbolAddress((void**)&ln,  g_ln);
    cudaGetSymbolAddress((void**)&qkv, g_qkv);
    cudaGetSymbolAddress((void**)&att, g_att);
    cudaGetSymbolAddress((void**)&hdn, g_hdn);

    dim3 tb(32, 8);
    dim3 tg(N_ / 32, C_ / 32, B_);

    // 1. tok = transpose(x) + pos
    transpose_in_kernel<<<tg, tb>>>(x, pos);
    // 2. ln1
    ln_kernel<<<BN_, C_>>>(tok, g1, beta1, ln);
    // 3. qkv = ln @ w_qkv
    sgemm_kernel<0><<<dim3(384 / BN, BN_ / BM), 256>>>(ln, w_qkv, nullptr, nullptr, qkv,
                                                       BN_, C_, 384);
    // 4. attention
    attn_kernel<<<dim3(N_ / 256, HEADS, B_), 256>>>(qkv, att);
    // 5. tok = att @ w_out + b_out + tok
    sgemm_kernel<1><<<dim3(C_ / BN, BN_ / BM), 256>>>(att, w_out, b_out, tok, tok,
                                                      BN_, INNER, C_);
    // 6. ln2
    ln_kernel<<<BN_, C_>>>(tok, g2, beta2, ln);
    // 7. hdn = gelu(ln @ w_ff1 + b_ff1)
    sgemm_kernel<2><<<dim3(INNER / BN, BN_ / BM), 256>>>(ln, w_ff1, b_ff1, nullptr, hdn,
                                                         BN_, C_, INNER);
    // 8. tok = hdn @ w_ff2 + b_ff2 + tok
    sgemm_kernel<1><<<dim3(C_ / BN, BN_ / BM), 256>>>(hdn, w_ff2, b_ff2, tok, tok,
                                                      BN_, INNER, C_);
    // 9. out = transpose(tok)
    transpose_out_kernel<<<tg, tb>>>(out);
}